// round 14
// baseline (speedup 1.0000x reference)
#include <cuda_runtime.h>
#include <cuda_bf16.h>
#include <cstdint>

// Problem constants
#define BB 2
#define SS 256
#define TT 128
#define EE 512     // ES == ET == 512
#define HH 1024

#define NHS 16                // h splits for attn (occupancy: 512 blocks)
#define HSP (HH / NHS)        // 64 h per split
#define OUTN (BB * TT * SS)   // 65536

#define GEMM_BLKS 96          // 6 M-blocks (128) x 16 N-blocks (64)

// ---------------- device scratch (no allocations allowed) ----------------
// NOTE: g_sL/g_tL hold tanh(sL), tanh(tL) (precomputed in proj epilogue).
__device__ float g_sL[BB * SS * HH];          // 2 MB
__device__ float g_tL[BB * TT * HH];          // 1 MB
__device__ float g_part[NHS * OUTN];          // 4 MB partials
__device__ int   g_cnt[BB * (TT / 32) * (SS / 64)];   // tile counters (zero-init)

__device__ __forceinline__ float tanh_fast(float x) {
    float y;
    asm("tanh.approx.f32 %0, %1;" : "=f"(y) : "f"(x));
    return y;
}
__device__ __forceinline__ float rcp_fast(float x) {
    float y;
    asm("rcp.approx.f32 %0, %1;" : "=f"(y) : "f"(x));
    return y;
}
__device__ __forceinline__ uint32_t sm_u32(const void* p) {
    return (uint32_t)__cvta_generic_to_shared(p);
}
__device__ __forceinline__ void ldsm_x4(uint32_t* r, uint32_t addr) {
    asm volatile("ldmatrix.sync.aligned.m8n8.x4.shared.b16 {%0,%1,%2,%3}, [%4];"
                 : "=r"(r[0]), "=r"(r[1]), "=r"(r[2]), "=r"(r[3]) : "r"(addr));
}
__device__ __forceinline__ void mma_bf16(float* d, const uint32_t* a, const uint32_t* b) {
    asm volatile(
        "mma.sync.aligned.m16n8k16.row.col.f32.bf16.bf16.f32 "
        "{%0,%1,%2,%3}, {%4,%5,%6,%7}, {%8,%9}, {%0,%1,%2,%3};\n"
        : "+f"(d[0]), "+f"(d[1]), "+f"(d[2]), "+f"(d[3])
        : "r"(a[0]), "r"(a[1]), "r"(a[2]), "r"(a[3]), "r"(b[0]), "r"(b[1]));
}
// fp32x4 -> (hi bf16x4, lo bf16x4) packed as uint2 each
__device__ __forceinline__ void cvt_hilo(const float4 v, uint2& hi, uint2& lo) {
    __nv_bfloat162 h01 = __floats2bfloat162_rn(v.x, v.y);
    __nv_bfloat162 h23 = __floats2bfloat162_rn(v.z, v.w);
    float2 f01 = __bfloat1622float2(h01);
    float2 f23 = __bfloat1622float2(h23);
    __nv_bfloat162 l01 = __floats2bfloat162_rn(v.x - f01.x, v.y - f01.y);
    __nv_bfloat162 l23 = __floats2bfloat162_rn(v.z - f23.x, v.w - f23.y);
    hi.x = *(uint32_t*)&h01; hi.y = *(uint32_t*)&h23;
    lo.x = *(uint32_t*)&l01; lo.y = *(uint32_t*)&l23;
}

// ---------------- fused projection GEMM (fp32 in, bf16-split mma) + gate ------
// blocks [0,96): GEMM tiles 128m x 64n; block 96: gate softmax.
// 3-term split per 32-k stage: Ahi*Whi + Ahi*Wlo + Alo*Whi, fp32 accum.
// Epilogue applies tanh -> g_sL/g_tL hold tanh of the projections.
__global__ __launch_bounds__(256, 1)
void proj_gate_kernel(const float* __restrict__ source,
                      const float* __restrict__ target,
                      const float* __restrict__ Ws,
                      const float* __restrict__ Wt,
                      const float* __restrict__ Wg,
                      const float* __restrict__ bg,
                      float* __restrict__ outg) {
    __shared__ __align__(16) __nv_bfloat16 AsH[128][40];
    __shared__ __align__(16) __nv_bfloat16 AsL[128][40];
    __shared__ __align__(16) __nv_bfloat16 BsH[64][40];
    __shared__ __align__(16) __nv_bfloat16 BsL[64][40];

    const int bx  = blockIdx.x;
    const int tid = threadIdx.x;

    if (bx >= GEMM_BLKS) {
        // ---- gate: softmax over 2 of target @ Wg^T + bg ----
        const int bt = tid;                            // 0..255
        const float4* tr = (const float4*)(target + (size_t)bt * EE);
        const float4* w0 = (const float4*)(Wg);
        const float4* w1 = (const float4*)(Wg + EE);
        float s0 = 0.f, s1 = 0.f;
#pragma unroll 8
        for (int e = 0; e < EE / 4; e++) {
            float4 t4 = tr[e];
            float4 a4 = w0[e];
            float4 b4 = w1[e];
            s0 = fmaf(t4.x, a4.x, fmaf(t4.y, a4.y, fmaf(t4.z, a4.z, fmaf(t4.w, a4.w, s0))));
            s1 = fmaf(t4.x, b4.x, fmaf(t4.y, b4.y, fmaf(t4.z, b4.z, fmaf(t4.w, b4.w, s1))));
        }
        float x0 = s0 + bg[0], x1 = s1 + bg[1];
        float m  = fmaxf(x0, x1);
        float e0 = expf(x0 - m), e1 = expf(x1 - m);
        float inv = 1.f / (e0 + e1);
        outg[bt * 2]     = e0 * inv;
        outg[bt * 2 + 1] = e1 * inv;
        return;
    }

    const int lane = tid & 31;
    const int w    = tid >> 5;
    const int row0 = (bx >> 4) * 128;     // combined-M (0..640)
    const int col0 = (bx & 15) * 64;      // N (h dim)

    const float* __restrict__ Aptr;
    const float* __restrict__ Wsel;
    int arow0;
    if (row0 < BB * SS) { Aptr = source; Wsel = Ws; arow0 = row0; }
    else                { Aptr = target; Wsel = Wt; arow0 = row0 - BB * SS; }

    const int arow = tid >> 1;            // 0..127
    const int acol = (tid & 1) * 16;      // 0 or 16
    const int brow = tid >> 2;            // 0..63
    const int bcol = (tid & 3) * 8;       // 0,8,16,24

    float acc[8][4];
#pragma unroll
    for (int j = 0; j < 8; j++)
#pragma unroll
        for (int i = 0; i < 4; i++) acc[j][i] = 0.f;

    float4 pa[4];
    float4 pb[2];
#pragma unroll
    for (int j = 0; j < 4; j++)
        pa[j] = *(const float4*)&Aptr[(size_t)(arow0 + arow) * EE + acol + j * 4];
#pragma unroll
    for (int j = 0; j < 2; j++)
        pb[j] = *(const float4*)&Wsel[(size_t)(col0 + brow) * EE + bcol + j * 4];

    const uint32_t aoff = (uint32_t)(((w * 16 + (lane & 15)) * 40 + (lane >> 4) * 8) * 2);
    const uint32_t boff = (uint32_t)((((lane >> 4) * 8 + (lane & 7)) * 40 + ((lane >> 3) & 1) * 8) * 2);
    const uint32_t aH = sm_u32(&AsH[0][0]) + aoff;
    const uint32_t aL = sm_u32(&AsL[0][0]) + aoff;
    const uint32_t bH = sm_u32(&BsH[0][0]) + boff;
    const uint32_t bL = sm_u32(&BsL[0][0]) + boff;

    for (int s = 0; s < EE / 32; s++) {
        if (s) __syncthreads();
#pragma unroll
        for (int j = 0; j < 4; j++) {
            uint2 hi, lo;
            cvt_hilo(pa[j], hi, lo);
            *(uint2*)&AsH[arow][acol + j * 4] = hi;
            *(uint2*)&AsL[arow][acol + j * 4] = lo;
        }
#pragma unroll
        for (int j = 0; j < 2; j++) {
            uint2 hi, lo;
            cvt_hilo(pb[j], hi, lo);
            *(uint2*)&BsH[brow][bcol + j * 4] = hi;
            *(uint2*)&BsL[brow][bcol + j * 4] = lo;
        }
        __syncthreads();

        if (s + 1 < EE / 32) {
            const int k0 = (s + 1) * 32;
#pragma unroll
            for (int j = 0; j < 4; j++)
                pa[j] = *(const float4*)&Aptr[(size_t)(arow0 + arow) * EE + k0 + acol + j * 4];
#pragma unroll
            for (int j = 0; j < 2; j++)
                pb[j] = *(const float4*)&Wsel[(size_t)(col0 + brow) * EE + k0 + bcol + j * 4];
        }

#pragma unroll
        for (int combo = 0; combo < 3; combo++) {
            const uint32_t abase = (combo == 2) ? aL : aH;
            const uint32_t bbase = (combo == 1) ? bL : bH;
#pragma unroll
            for (int h = 0; h < 2; h++) {
                uint32_t aF[4];
                ldsm_x4(aF, abase + h * 32);
#pragma unroll
                for (int jp = 0; jp < 4; jp++) {
                    uint32_t bF[4];
                    ldsm_x4(bF, bbase + jp * 16 * 80 + h * 32);
                    mma_bf16(acc[jp * 2],     aF, bF);
                    mma_bf16(acc[jp * 2 + 1], aF, bF + 2);
                }
            }
        }
    }

    // epilogue: apply tanh, write to g_sL / g_tL
    const int mrow = row0 + w * 16 + (lane >> 2);
    float* C;
    int cr;
    if (row0 < BB * SS) { C = g_sL; cr = mrow; }
    else                { C = g_tL; cr = mrow - BB * SS; }
#pragma unroll
    for (int j = 0; j < 8; j++) {
        const int ccol = col0 + j * 8 + (lane & 3) * 2;
        *(float2*)&C[(size_t)cr * HH + ccol] =
            make_float2(tanh_fast(acc[j][0]), tanh_fast(acc[j][1]));
        *(float2*)&C[(size_t)(cr + 8) * HH + ccol] =
            make_float2(tanh_fast(acc[j][2]), tanh_fast(acc[j][3]));
    }
}

// ---------------- additive attention via tanh addition identity --------------
// tanh(s+t) = (ts + tt) / (1 + ts*tt), ts/tt precomputed. Per element:
// FADD(num) + FFMA(den) + FMUL(wnum, overlaps rcp) + rcp + FFMA(acc).
// NHS=16 -> 512 blocks (~3.5/SM, occupancy ~44%) for latency hiding.
__global__ void attn_kernel(const float* __restrict__ Wr,
                            const float* __restrict__ maskF,
                            const float* __restrict__ br,
                            float* __restrict__ out) {
    __shared__ float sSh[32][65];
    __shared__ float tSh[32][33];
    __shared__ float wrS[HSP];
    __shared__ int lastFlag;

    const int tid = threadIdx.x;
    const int tx = tid & 15;       // s micro: s = s0 + tx*4 .. +3
    const int ty = tid >> 4;       // t micro: t = t0 + ty*2 .. +1

    const int s0 = blockIdx.x * 64;
    const int t0 = blockIdx.y * 32;
    const int bz = blockIdx.z;
    const int b  = bz & 1;
    const int hs = bz >> 1;        // 0..15
    const int h0 = hs * HSP;

    if (tid < HSP) wrS[tid] = Wr[h0 + tid];

    const int lk = tid & 31;       // h lane
    const int lr = tid >> 5;       // 0..7

    const float* __restrict__ sLb = g_sL + ((size_t)b * SS + s0) * HH + h0;
    const float* __restrict__ tLb = g_tL + ((size_t)b * TT + t0) * HH + h0;

    float a[2][4];
#pragma unroll
    for (int j = 0; j < 2; j++)
#pragma unroll
        for (int i = 0; i < 4; i++) a[j][i] = 0.f;

    for (int cc = 0; cc < HSP / 32; cc++) {
        const int hc = cc * 32;
        if (cc) __syncthreads();
#pragma unroll
        for (int p = 0; p < 8; p++) {
            const int r = lr + 8 * p;
            sSh[lk][r] = sLb[(size_t)r * HH + hc + lk];
        }
#pragma unroll
        for (int p = 0; p < 4; p++) {
            const int r = lr + 8 * p;
            tSh[lk][r] = tLb[(size_t)r * HH + hc + lk];
        }
        __syncthreads();

#pragma unroll 8
        for (int kk = 0; kk < 32; kk++) {
            const float w   = wrS[hc + kk];
            const float t0v = tSh[kk][ty * 2];
            const float t1v = tSh[kk][ty * 2 + 1];
            const float sv0 = sSh[kk][tx * 4];
            const float sv1 = sSh[kk][tx * 4 + 1];
            const float sv2 = sSh[kk][tx * 4 + 2];
            const float sv3 = sSh[kk][tx * 4 + 3];
#define TACC(J, TV, SV)                                                  \
            {                                                            \
                float num  = TV + SV;                                    \
                float den  = fmaf(TV, SV, 1.0f);                         \
                float wnum = w * num;         /* overlaps rcp latency */ \
                float r    = rcp_fast(den);                              \
                a[J >> 2][J & 3] = fmaf(wnum, r, a[J >> 2][J & 3]);      \
            }
            TACC(0, t0v, sv0) TACC(1, t0v, sv1) TACC(2, t0v, sv2) TACC(3, t0v, sv3)
            TACC(4, t1v, sv0) TACC(5, t1v, sv1) TACC(6, t1v, sv2) TACC(7, t1v, sv3)
#undef TACC
        }
    }

    // ---- write partials ----
    const int t = t0 + ty * 2;
    const int s = s0 + tx * 4;
    const int idx = (b * TT + t) * SS + s;
#pragma unroll
    for (int j = 0; j < 2; j++) {
        float4 o = make_float4(a[j][0], a[j][1], a[j][2], a[j][3]);
        *(float4*)&g_part[hs * OUTN + idx + j * SS] = o;
    }

    // ---- ticket: last h-split block reduces the tile ----
    __threadfence();
    __syncthreads();
    const int tile = (b * (TT / 32) + blockIdx.y) * (SS / 64) + blockIdx.x;
    if (tid == 0) lastFlag = (atomicAdd(&g_cnt[tile], 1) == NHS - 1);
    __syncthreads();
    if (!lastFlag) return;

    const float bias = br[0];
    const float ninf = __int_as_float(0xff800000);
#pragma unroll
    for (int j = 0; j < 2; j++) {
        float4 acc4 = make_float4(0.f, 0.f, 0.f, 0.f);
#pragma unroll
        for (int h = 0; h < NHS; h++) {
            const float4 p = __ldcg((const float4*)&g_part[h * OUTN + idx + j * SS]);
            acc4.x += p.x; acc4.y += p.y; acc4.z += p.z; acc4.w += p.w;
        }
        float4 res;
        res.x = (__float_as_uint(maskF[b * SS + s])     != 0u) ? (acc4.x + bias) : ninf;
        res.y = (__float_as_uint(maskF[b * SS + s + 1]) != 0u) ? (acc4.y + bias) : ninf;
        res.z = (__float_as_uint(maskF[b * SS + s + 2]) != 0u) ? (acc4.z + bias) : ninf;
        res.w = (__float_as_uint(maskF[b * SS + s + 3]) != 0u) ? (acc4.w + bias) : ninf;
        *(float4*)&out[idx + j * SS] = res;
    }
    if (tid == 0) g_cnt[tile] = 0;   // reset for next graph replay
}

// ---------------- launch ----------------
extern "C" void kernel_launch(void* const* d_in, const int* in_sizes, int n_in,
                              void* d_out, int out_size) {
    const float* source = (const float*)d_in[0];  // [B,S,ES]
    const float* target = (const float*)d_in[1];  // [B,T,ET]
    const float* maskF  = (const float*)d_in[2];  // [B,S] bool (promoted to f32)
    const float* Ws     = (const float*)d_in[3];  // [H,ES]
    const float* Wt     = (const float*)d_in[4];  // [H,ET]
    const float* Wr     = (const float*)d_in[5];  // [H]
    const float* br     = (const float*)d_in[6];  // scalar
    const float* Wg     = (const float*)d_in[7];  // [2,ET]
    const float* bg     = (const float*)d_in[8];  // [2]

    float* out      = (float*)d_out;
    float* out_gate = out + (out_size - BB * TT * 2);

    proj_gate_kernel<<<GEMM_BLKS + 1, 256>>>(source, target, Ws, Wt, Wg, bg, out_gate);
    attn_kernel<<<dim3(SS / 64, TT / 32, BB * NHS), 256>>>(Wr, maskF, br, out);
}

// round 16
// speedup vs baseline: 1.2066x; 1.2066x over previous
#include <cuda_runtime.h>
#include <cuda_bf16.h>
#include <cstdint>

// Problem constants
#define BB 2
#define SS 256
#define TT 128
#define EE 512     // ES == ET == 512
#define HH 1024

#define NHS 8                 // h splits for attn
#define HSP (HH / NHS)        // 128 h per split
#define OUTN (BB * TT * SS)   // 65536

#define GEMM_BLKS 96          // 6 M-blocks (128) x 16 N-blocks (64)

// ---------------- device scratch (no allocations allowed) ----------------
__device__ float g_sL[BB * SS * HH];          // 2 MB  (raw projections)
__device__ float g_tL[BB * TT * HH];          // 1 MB
__device__ float g_part[NHS * OUTN];          // 2 MB partials
__device__ int   g_cnt[BB * (TT / 32) * (SS / 64)];   // tile counters (zero-init)

__device__ __forceinline__ float tanh_fast(float x) {
    float y;
    asm("tanh.approx.f32 %0, %1;" : "=f"(y) : "f"(x));
    return y;
}
__device__ __forceinline__ uint32_t sm_u32(const void* p) {
    return (uint32_t)__cvta_generic_to_shared(p);
}
__device__ __forceinline__ void ldsm_x4(uint32_t* r, uint32_t addr) {
    asm volatile("ldmatrix.sync.aligned.m8n8.x4.shared.b16 {%0,%1,%2,%3}, [%4];"
                 : "=r"(r[0]), "=r"(r[1]), "=r"(r[2]), "=r"(r[3]) : "r"(addr));
}
__device__ __forceinline__ void mma_bf16(float* d, const uint32_t* a, const uint32_t* b) {
    asm volatile(
        "mma.sync.aligned.m16n8k16.row.col.f32.bf16.bf16.f32 "
        "{%0,%1,%2,%3}, {%4,%5,%6,%7}, {%8,%9}, {%0,%1,%2,%3};\n"
        : "+f"(d[0]), "+f"(d[1]), "+f"(d[2]), "+f"(d[3])
        : "r"(a[0]), "r"(a[1]), "r"(a[2]), "r"(a[3]), "r"(b[0]), "r"(b[1]));
}
// fp32x4 -> (hi bf16x4, lo bf16x4) packed as uint2 each
__device__ __forceinline__ void cvt_hilo(const float4 v, uint2& hi, uint2& lo) {
    __nv_bfloat162 h01 = __floats2bfloat162_rn(v.x, v.y);
    __nv_bfloat162 h23 = __floats2bfloat162_rn(v.z, v.w);
    float2 f01 = __bfloat1622float2(h01);
    float2 f23 = __bfloat1622float2(h23);
    __nv_bfloat162 l01 = __floats2bfloat162_rn(v.x - f01.x, v.y - f01.y);
    __nv_bfloat162 l23 = __floats2bfloat162_rn(v.z - f23.x, v.w - f23.y);
    hi.x = *(uint32_t*)&h01; hi.y = *(uint32_t*)&h23;
    lo.x = *(uint32_t*)&l01; lo.y = *(uint32_t*)&l23;
}

// ---------------- fused projection GEMM (fp32 in, bf16-split mma) + gate ------
// blocks [0,96): GEMM tiles 128m x 64n; block 96: gate softmax.
// 3-term split per 32-k stage: Ahi*Whi + Ahi*Wlo + Alo*Whi, fp32 accum.
// Fragment reuse: A frags held across combos; each B frag loaded once per (jp,h)
// and used by both the (H,*) and (L,H) combos -> 20 ldsm/stage (was 30).
__global__ __launch_bounds__(256, 1)
void proj_gate_kernel(const float* __restrict__ source,
                      const float* __restrict__ target,
                      const float* __restrict__ Ws,
                      const float* __restrict__ Wt,
                      const float* __restrict__ Wg,
                      const float* __restrict__ bg,
                      float* __restrict__ outg) {
    __shared__ __align__(16) __nv_bfloat16 AsH[128][40];
    __shared__ __align__(16) __nv_bfloat16 AsL[128][40];
    __shared__ __align__(16) __nv_bfloat16 BsH[64][40];
    __shared__ __align__(16) __nv_bfloat16 BsL[64][40];

    const int bx  = blockIdx.x;
    const int tid = threadIdx.x;

    if (bx >= GEMM_BLKS) {
        // ---- gate: softmax over 2 of target @ Wg^T + bg ----
        const int bt = tid;                            // 0..255
        const float4* tr = (const float4*)(target + (size_t)bt * EE);
        const float4* w0 = (const float4*)(Wg);
        const float4* w1 = (const float4*)(Wg + EE);
        float s0 = 0.f, s1 = 0.f;
#pragma unroll 8
        for (int e = 0; e < EE / 4; e++) {
            float4 t4 = tr[e];
            float4 a4 = w0[e];
            float4 b4 = w1[e];
            s0 = fmaf(t4.x, a4.x, fmaf(t4.y, a4.y, fmaf(t4.z, a4.z, fmaf(t4.w, a4.w, s0))));
            s1 = fmaf(t4.x, b4.x, fmaf(t4.y, b4.y, fmaf(t4.z, b4.z, fmaf(t4.w, b4.w, s1))));
        }
        float x0 = s0 + bg[0], x1 = s1 + bg[1];
        float m  = fmaxf(x0, x1);
        float e0 = expf(x0 - m), e1 = expf(x1 - m);
        float inv = 1.f / (e0 + e1);
        outg[bt * 2]     = e0 * inv;
        outg[bt * 2 + 1] = e1 * inv;
        return;
    }

    const int lane = tid & 31;
    const int w    = tid >> 5;
    const int row0 = (bx >> 4) * 128;     // combined-M (0..640)
    const int col0 = (bx & 15) * 64;      // N (h dim)

    const float* __restrict__ Aptr;
    const float* __restrict__ Wsel;
    int arow0;
    if (row0 < BB * SS) { Aptr = source; Wsel = Ws; arow0 = row0; }
    else                { Aptr = target; Wsel = Wt; arow0 = row0 - BB * SS; }

    const int arow = tid >> 1;            // 0..127
    const int acol = (tid & 1) * 16;      // 0 or 16
    const int brow = tid >> 2;            // 0..63
    const int bcol = (tid & 3) * 8;       // 0,8,16,24

    float acc[8][4];
#pragma unroll
    for (int j = 0; j < 8; j++)
#pragma unroll
        for (int i = 0; i < 4; i++) acc[j][i] = 0.f;

    float4 pa[4];
    float4 pb[2];
#pragma unroll
    for (int j = 0; j < 4; j++)
        pa[j] = *(const float4*)&Aptr[(size_t)(arow0 + arow) * EE + acol + j * 4];
#pragma unroll
    for (int j = 0; j < 2; j++)
        pb[j] = *(const float4*)&Wsel[(size_t)(col0 + brow) * EE + bcol + j * 4];

    const uint32_t aoff = (uint32_t)(((w * 16 + (lane & 15)) * 40 + (lane >> 4) * 8) * 2);
    const uint32_t boff = (uint32_t)((((lane >> 4) * 8 + (lane & 7)) * 40 + ((lane >> 3) & 1) * 8) * 2);
    const uint32_t aH = sm_u32(&AsH[0][0]) + aoff;
    const uint32_t aL = sm_u32(&AsL[0][0]) + aoff;
    const uint32_t bH = sm_u32(&BsH[0][0]) + boff;
    const uint32_t bL = sm_u32(&BsL[0][0]) + boff;

    for (int s = 0; s < EE / 32; s++) {
        if (s) __syncthreads();
#pragma unroll
        for (int j = 0; j < 4; j++) {
            uint2 hi, lo;
            cvt_hilo(pa[j], hi, lo);
            *(uint2*)&AsH[arow][acol + j * 4] = hi;
            *(uint2*)&AsL[arow][acol + j * 4] = lo;
        }
#pragma unroll
        for (int j = 0; j < 2; j++) {
            uint2 hi, lo;
            cvt_hilo(pb[j], hi, lo);
            *(uint2*)&BsH[brow][bcol + j * 4] = hi;
            *(uint2*)&BsL[brow][bcol + j * 4] = lo;
        }
        __syncthreads();

        if (s + 1 < EE / 32) {
            const int k0 = (s + 1) * 32;
#pragma unroll
            for (int j = 0; j < 4; j++)
                pa[j] = *(const float4*)&Aptr[(size_t)(arow0 + arow) * EE + k0 + acol + j * 4];
#pragma unroll
            for (int j = 0; j < 2; j++)
                pb[j] = *(const float4*)&Wsel[(size_t)(col0 + brow) * EE + k0 + bcol + j * 4];
        }

        // A fragments for both h halves, hi and lo (4 ldsm)
        uint32_t aHf[2][4], aLf[2][4];
#pragma unroll
        for (int h = 0; h < 2; h++) {
            ldsm_x4(aHf[h], aH + h * 32);
            ldsm_x4(aLf[h], aL + h * 32);
        }
        // B fragments loaded once per (jp,h), reused across 3 combos (16 ldsm)
#pragma unroll
        for (int jp = 0; jp < 4; jp++) {
#pragma unroll
            for (int h = 0; h < 2; h++) {
                uint32_t bHf[4], bLf[4];
                ldsm_x4(bHf, bH + jp * 16 * 80 + h * 32);
                ldsm_x4(bLf, bL + jp * 16 * 80 + h * 32);
                mma_bf16(acc[jp * 2],     aHf[h], bHf);
                mma_bf16(acc[jp * 2 + 1], aHf[h], bHf + 2);
                mma_bf16(acc[jp * 2],     aHf[h], bLf);
                mma_bf16(acc[jp * 2 + 1], aHf[h], bLf + 2);
                mma_bf16(acc[jp * 2],     aLf[h], bHf);
                mma_bf16(acc[jp * 2 + 1], aLf[h], bHf + 2);
            }
        }
    }

    // epilogue: write raw fp32 projections to g_sL / g_tL
    const int mrow = row0 + w * 16 + (lane >> 2);
    float* C;
    int cr;
    if (row0 < BB * SS) { C = g_sL; cr = mrow; }
    else                { C = g_tL; cr = mrow - BB * SS; }
#pragma unroll
    for (int j = 0; j < 8; j++) {
        const int ccol = col0 + j * 8 + (lane & 3) * 2;
        *(float2*)&C[(size_t)cr * HH + ccol]       = make_float2(acc[j][0], acc[j][1]);
        *(float2*)&C[(size_t)(cr + 8) * HH + ccol] = make_float2(acc[j][2], acc[j][3]);
    }
}

// ---------------- additive attention (R9 proven: native tanh, 29.3us) --------
// grid (S/64, T/32, B*NHS), 256 threads. Tile 32t x 64s x 128h, microtile 2t x 4s.
__global__ void attn_kernel(const float* __restrict__ Wr,
                            const float* __restrict__ maskF,
                            const float* __restrict__ br,
                            float* __restrict__ out) {
    __shared__ float sSh[32][65];
    __shared__ float tSh[32][33];
    __shared__ float wrS[HSP];
    __shared__ int lastFlag;

    const int tid = threadIdx.x;
    const int tx = tid & 15;       // s micro: s = s0 + tx*4 .. +3
    const int ty = tid >> 4;       // t micro: t = t0 + ty*2 .. +1

    const int s0 = blockIdx.x * 64;
    const int t0 = blockIdx.y * 32;
    const int bz = blockIdx.z;
    const int b  = bz & 1;
    const int hs = bz >> 1;
    const int h0 = hs * HSP;

    if (tid < HSP) wrS[tid] = Wr[h0 + tid];

    const int lk = tid & 31;       // h lane
    const int lr = tid >> 5;       // 0..7

    const float* __restrict__ sLb = g_sL + ((size_t)b * SS + s0) * HH + h0;
    const float* __restrict__ tLb = g_tL + ((size_t)b * TT + t0) * HH + h0;

    float a[2][4];
#pragma unroll
    for (int j = 0; j < 2; j++)
#pragma unroll
        for (int i = 0; i < 4; i++) a[j][i] = 0.f;

    for (int cc = 0; cc < HSP / 32; cc++) {
        const int hc = cc * 32;
        if (cc) __syncthreads();
#pragma unroll
        for (int p = 0; p < 8; p++) {
            const int r = lr + 8 * p;
            sSh[lk][r] = sLb[(size_t)r * HH + hc + lk];
        }
#pragma unroll
        for (int p = 0; p < 4; p++) {
            const int r = lr + 8 * p;
            tSh[lk][r] = tLb[(size_t)r * HH + hc + lk];
        }
        __syncthreads();

#pragma unroll 8
        for (int kk = 0; kk < 32; kk++) {
            const float w  = wrS[hc + kk];
            const float t0v = tSh[kk][ty * 2];
            const float t1v = tSh[kk][ty * 2 + 1];
            float sv0 = sSh[kk][tx * 4];
            float sv1 = sSh[kk][tx * 4 + 1];
            float sv2 = sSh[kk][tx * 4 + 2];
            float sv3 = sSh[kk][tx * 4 + 3];
            a[0][0] = fmaf(w, tanh_fast(t0v + sv0), a[0][0]);
            a[0][1] = fmaf(w, tanh_fast(t0v + sv1), a[0][1]);
            a[0][2] = fmaf(w, tanh_fast(t0v + sv2), a[0][2]);
            a[0][3] = fmaf(w, tanh_fast(t0v + sv3), a[0][3]);
            a[1][0] = fmaf(w, tanh_fast(t1v + sv0), a[1][0]);
            a[1][1] = fmaf(w, tanh_fast(t1v + sv1), a[1][1]);
            a[1][2] = fmaf(w, tanh_fast(t1v + sv2), a[1][2]);
            a[1][3] = fmaf(w, tanh_fast(t1v + sv3), a[1][3]);
        }
    }

    // ---- write partials ----
    const int t = t0 + ty * 2;
    const int s = s0 + tx * 4;
    const int idx = (b * TT + t) * SS + s;
#pragma unroll
    for (int j = 0; j < 2; j++) {
        float4 o = make_float4(a[j][0], a[j][1], a[j][2], a[j][3]);
        *(float4*)&g_part[hs * OUTN + idx + j * SS] = o;
    }

    // ---- ticket: last h-split block reduces the tile ----
    __threadfence();
    __syncthreads();
    const int tile = (b * (TT / 32) + blockIdx.y) * (SS / 64) + blockIdx.x;
    if (tid == 0) lastFlag = (atomicAdd(&g_cnt[tile], 1) == NHS - 1);
    __syncthreads();
    if (!lastFlag) return;

    const float bias = br[0];
    const float ninf = __int_as_float(0xff800000);
#pragma unroll
    for (int j = 0; j < 2; j++) {
        float4 acc4 = make_float4(0.f, 0.f, 0.f, 0.f);
#pragma unroll
        for (int h = 0; h < NHS; h++) {
            const float4 p = __ldcg((const float4*)&g_part[h * OUTN + idx + j * SS]);
            acc4.x += p.x; acc4.y += p.y; acc4.z += p.z; acc4.w += p.w;
        }
        float4 res;
        res.x = (__float_as_uint(maskF[b * SS + s])     != 0u) ? (acc4.x + bias) : ninf;
        res.y = (__float_as_uint(maskF[b * SS + s + 1]) != 0u) ? (acc4.y + bias) : ninf;
        res.z = (__float_as_uint(maskF[b * SS + s + 2]) != 0u) ? (acc4.z + bias) : ninf;
        res.w = (__float_as_uint(maskF[b * SS + s + 3]) != 0u) ? (acc4.w + bias) : ninf;
        *(float4*)&out[idx + j * SS] = res;
    }
    if (tid == 0) g_cnt[tile] = 0;   // reset for next graph replay
}

// ---------------- launch ----------------
extern "C" void kernel_launch(void* const* d_in, const int* in_sizes, int n_in,
                              void* d_out, int out_size) {
    const float* source = (const float*)d_in[0];  // [B,S,ES]
    const float* target = (const float*)d_in[1];  // [B,T,ET]
    const float* maskF  = (const float*)d_in[2];  // [B,S] bool (promoted to f32)
    const float* Ws     = (const float*)d_in[3];  // [H,ES]
    const float* Wt     = (const float*)d_in[4];  // [H,ET]
    const float* Wr     = (const float*)d_in[5];  // [H]
    const float* br     = (const float*)d_in[6];  // scalar
    const float* Wg     = (const float*)d_in[7];  // [2,ET]
    const float* bg     = (const float*)d_in[8];  // [2]

    float* out      = (float*)d_out;
    float* out_gate = out + (out_size - BB * TT * 2);

    proj_gate_kernel<<<GEMM_BLKS + 1, 256>>>(source, target, Ws, Wt, Wg, bg, out_gate);
    attn_kernel<<<dim3(SS / 64, TT / 32, BB * NHS), 256>>>(Wr, maskF, br, out);
}

// round 17
// speedup vs baseline: 1.2154x; 1.0073x over previous
#include <cuda_runtime.h>
#include <cuda_bf16.h>
#include <cuda_fp16.h>
#include <cstdint>

// Problem constants
#define BB 2
#define SS 256
#define TT 128
#define EE 512     // ES == ET == 512
#define HH 1024

#define NHS 8                 // h splits for attn
#define HSP (HH / NHS)        // 128 h per split
#define OUTN (BB * TT * SS)   // 65536

#define GEMM_BLKS 96          // 6 M-blocks (128) x 16 N-blocks (64)

// ---------------- device scratch (no allocations allowed) ----------------
__device__ float g_sL[BB * SS * HH];          // 2 MB  (raw projections)
__device__ float g_tL[BB * TT * HH];          // 1 MB
__device__ float g_part[NHS * OUTN];          // 2 MB partials
__device__ int   g_cnt[BB * (TT / 32) * (SS / 64)];   // tile counters (zero-init)

__device__ __forceinline__ uint32_t sm_u32(const void* p) {
    return (uint32_t)__cvta_generic_to_shared(p);
}
__device__ __forceinline__ void ldsm_x4(uint32_t* r, uint32_t addr) {
    asm volatile("ldmatrix.sync.aligned.m8n8.x4.shared.b16 {%0,%1,%2,%3}, [%4];"
                 : "=r"(r[0]), "=r"(r[1]), "=r"(r[2]), "=r"(r[3]) : "r"(addr));
}
__device__ __forceinline__ void mma_bf16(float* d, const uint32_t* a, const uint32_t* b) {
    asm volatile(
        "mma.sync.aligned.m16n8k16.row.col.f32.bf16.bf16.f32 "
        "{%0,%1,%2,%3}, {%4,%5,%6,%7}, {%8,%9}, {%0,%1,%2,%3};\n"
        : "+f"(d[0]), "+f"(d[1]), "+f"(d[2]), "+f"(d[3])
        : "r"(a[0]), "r"(a[1]), "r"(a[2]), "r"(a[3]), "r"(b[0]), "r"(b[1]));
}
// fp32x4 -> (hi bf16x4, lo bf16x4) packed as uint2 each
__device__ __forceinline__ void cvt_hilo(const float4 v, uint2& hi, uint2& lo) {
    __nv_bfloat162 h01 = __floats2bfloat162_rn(v.x, v.y);
    __nv_bfloat162 h23 = __floats2bfloat162_rn(v.z, v.w);
    float2 f01 = __bfloat1622float2(h01);
    float2 f23 = __bfloat1622float2(h23);
    __nv_bfloat162 l01 = __floats2bfloat162_rn(v.x - f01.x, v.y - f01.y);
    __nv_bfloat162 l23 = __floats2bfloat162_rn(v.z - f23.x, v.w - f23.y);
    hi.x = *(uint32_t*)&h01; hi.y = *(uint32_t*)&h23;
    lo.x = *(uint32_t*)&l01; lo.y = *(uint32_t*)&l23;
}
// tanh of two fp32 values via one MUFU tanh.approx.f16x2
__device__ __forceinline__ void tanh2_f16(float x0, float x1, float& y0, float& y1) {
    uint32_t p, q;
    asm("cvt.rn.f16x2.f32 %0, %1, %2;" : "=r"(p) : "f"(x1), "f"(x0)); // hi=x1, lo=x0
    asm("tanh.approx.f16x2 %0, %1;" : "=r"(q) : "r"(p));
    asm("{\n\t.reg .f16 lo, hi;\n\tmov.b32 {lo, hi}, %2;\n\t"
        "cvt.f32.f16 %0, lo;\n\tcvt.f32.f16 %1, hi;\n\t}"
        : "=f"(y0), "=f"(y1) : "r"(q));
}

// ---------------- fused projection GEMM (fp32 in, bf16-split mma) + gate ------
// blocks [0,96): GEMM tiles 128m x 64n; block 96: gate softmax.
// 3-term split per 32-k stage: Ahi*Whi + Ahi*Wlo + Alo*Whi, fp32 accum.
__global__ __launch_bounds__(256, 1)
void proj_gate_kernel(const float* __restrict__ source,
                      const float* __restrict__ target,
                      const float* __restrict__ Ws,
                      const float* __restrict__ Wt,
                      const float* __restrict__ Wg,
                      const float* __restrict__ bg,
                      float* __restrict__ outg) {
    __shared__ __align__(16) __nv_bfloat16 AsH[128][40];
    __shared__ __align__(16) __nv_bfloat16 AsL[128][40];
    __shared__ __align__(16) __nv_bfloat16 BsH[64][40];
    __shared__ __align__(16) __nv_bfloat16 BsL[64][40];

    const int bx  = blockIdx.x;
    const int tid = threadIdx.x;

    if (bx >= GEMM_BLKS) {
        // ---- gate: softmax over 2 of target @ Wg^T + bg ----
        const int bt = tid;                            // 0..255
        const float4* tr = (const float4*)(target + (size_t)bt * EE);
        const float4* w0 = (const float4*)(Wg);
        const float4* w1 = (const float4*)(Wg + EE);
        float s0 = 0.f, s1 = 0.f;
#pragma unroll 8
        for (int e = 0; e < EE / 4; e++) {
            float4 t4 = tr[e];
            float4 a4 = w0[e];
            float4 b4 = w1[e];
            s0 = fmaf(t4.x, a4.x, fmaf(t4.y, a4.y, fmaf(t4.z, a4.z, fmaf(t4.w, a4.w, s0))));
            s1 = fmaf(t4.x, b4.x, fmaf(t4.y, b4.y, fmaf(t4.z, b4.z, fmaf(t4.w, b4.w, s1))));
        }
        float x0 = s0 + bg[0], x1 = s1 + bg[1];
        float m  = fmaxf(x0, x1);
        float e0 = expf(x0 - m), e1 = expf(x1 - m);
        float inv = 1.f / (e0 + e1);
        outg[bt * 2]     = e0 * inv;
        outg[bt * 2 + 1] = e1 * inv;
        return;
    }

    const int lane = tid & 31;
    const int w    = tid >> 5;
    const int row0 = (bx >> 4) * 128;     // combined-M (0..640)
    const int col0 = (bx & 15) * 64;      // N (h dim)

    const float* __restrict__ Aptr;
    const float* __restrict__ Wsel;
    int arow0;
    if (row0 < BB * SS) { Aptr = source; Wsel = Ws; arow0 = row0; }
    else                { Aptr = target; Wsel = Wt; arow0 = row0 - BB * SS; }

    const int arow = tid >> 1;            // 0..127
    const int acol = (tid & 1) * 16;      // 0 or 16
    const int brow = tid >> 2;            // 0..63
    const int bcol = (tid & 3) * 8;       // 0,8,16,24

    float acc[8][4];
#pragma unroll
    for (int j = 0; j < 8; j++)
#pragma unroll
        for (int i = 0; i < 4; i++) acc[j][i] = 0.f;

    float4 pa[4];
    float4 pb[2];
#pragma unroll
    for (int j = 0; j < 4; j++)
        pa[j] = *(const float4*)&Aptr[(size_t)(arow0 + arow) * EE + acol + j * 4];
#pragma unroll
    for (int j = 0; j < 2; j++)
        pb[j] = *(const float4*)&Wsel[(size_t)(col0 + brow) * EE + bcol + j * 4];

    const uint32_t aoff = (uint32_t)(((w * 16 + (lane & 15)) * 40 + (lane >> 4) * 8) * 2);
    const uint32_t boff = (uint32_t)((((lane >> 4) * 8 + (lane & 7)) * 40 + ((lane >> 3) & 1) * 8) * 2);
    const uint32_t aH = sm_u32(&AsH[0][0]) + aoff;
    const uint32_t aL = sm_u32(&AsL[0][0]) + aoff;
    const uint32_t bH = sm_u32(&BsH[0][0]) + boff;
    const uint32_t bL = sm_u32(&BsL[0][0]) + boff;

    for (int s = 0; s < EE / 32; s++) {
        if (s) __syncthreads();
#pragma unroll
        for (int j = 0; j < 4; j++) {
            uint2 hi, lo;
            cvt_hilo(pa[j], hi, lo);
            *(uint2*)&AsH[arow][acol + j * 4] = hi;
            *(uint2*)&AsL[arow][acol + j * 4] = lo;
        }
#pragma unroll
        for (int j = 0; j < 2; j++) {
            uint2 hi, lo;
            cvt_hilo(pb[j], hi, lo);
            *(uint2*)&BsH[brow][bcol + j * 4] = hi;
            *(uint2*)&BsL[brow][bcol + j * 4] = lo;
        }
        __syncthreads();

        if (s + 1 < EE / 32) {
            const int k0 = (s + 1) * 32;
#pragma unroll
            for (int j = 0; j < 4; j++)
                pa[j] = *(const float4*)&Aptr[(size_t)(arow0 + arow) * EE + k0 + acol + j * 4];
#pragma unroll
            for (int j = 0; j < 2; j++)
                pb[j] = *(const float4*)&Wsel[(size_t)(col0 + brow) * EE + k0 + bcol + j * 4];
        }

        // A fragments for both h halves, hi and lo (4 ldsm)
        uint32_t aHf[2][4], aLf[2][4];
#pragma unroll
        for (int h = 0; h < 2; h++) {
            ldsm_x4(aHf[h], aH + h * 32);
            ldsm_x4(aLf[h], aL + h * 32);
        }
        // B fragments loaded once per (jp,h), reused across 3 combos
#pragma unroll
        for (int jp = 0; jp < 4; jp++) {
#pragma unroll
            for (int h = 0; h < 2; h++) {
                uint32_t bHf[4], bLf[4];
                ldsm_x4(bHf, bH + jp * 16 * 80 + h * 32);
                ldsm_x4(bLf, bL + jp * 16 * 80 + h * 32);
                mma_bf16(acc[jp * 2],     aHf[h], bHf);
                mma_bf16(acc[jp * 2 + 1], aHf[h], bHf + 2);
                mma_bf16(acc[jp * 2],     aHf[h], bLf);
                mma_bf16(acc[jp * 2 + 1], aHf[h], bLf + 2);
                mma_bf16(acc[jp * 2],     aLf[h], bHf);
                mma_bf16(acc[jp * 2 + 1], aLf[h], bHf + 2);
            }
        }
    }

    // epilogue: write raw fp32 projections to g_sL / g_tL
    const int mrow = row0 + w * 16 + (lane >> 2);
    float* C;
    int cr;
    if (row0 < BB * SS) { C = g_sL; cr = mrow; }
    else                { C = g_tL; cr = mrow - BB * SS; }
#pragma unroll
    for (int j = 0; j < 8; j++) {
        const int ccol = col0 + j * 8 + (lane & 3) * 2;
        *(float2*)&C[(size_t)cr * HH + ccol]       = make_float2(acc[j][0], acc[j][1]);
        *(float2*)&C[(size_t)(cr + 8) * HH + ccol] = make_float2(acc[j][2], acc[j][3]);
    }
}

// ---------------- additive attention: f16x2 tanh (2 elems / MUFU op) ---------
// grid (S/64, T/32, B*NHS), 256 threads. Tile 32t x 64s x 128h, microtile 2t x 4s.
// Pair elements along t: tanh2_f16(t0+sv, t1+sv) -> one tanh.approx.f16x2.
__global__ void attn_kernel(const float* __restrict__ Wr,
                            const float* __restrict__ maskF,
                            const float* __restrict__ br,
                            float* __restrict__ out) {
    __shared__ float sSh[32][65];
    __shared__ float tSh[32][33];
    __shared__ float wrS[HSP];
    __shared__ int lastFlag;

    const int tid = threadIdx.x;
    const int tx = tid & 15;       // s micro: s = s0 + tx*4 .. +3
    const int ty = tid >> 4;       // t micro: t = t0 + ty*2 .. +1

    const int s0 = blockIdx.x * 64;
    const int t0 = blockIdx.y * 32;
    const int bz = blockIdx.z;
    const int b  = bz & 1;
    const int hs = bz >> 1;
    const int h0 = hs * HSP;

    if (tid < HSP) wrS[tid] = Wr[h0 + tid];

    const int lk = tid & 31;       // h lane
    const int lr = tid >> 5;       // 0..7

    const float* __restrict__ sLb = g_sL + ((size_t)b * SS + s0) * HH + h0;
    const float* __restrict__ tLb = g_tL + ((size_t)b * TT + t0) * HH + h0;

    float a[2][4];
#pragma unroll
    for (int j = 0; j < 2; j++)
#pragma unroll
        for (int i = 0; i < 4; i++) a[j][i] = 0.f;

    for (int cc = 0; cc < HSP / 32; cc++) {
        const int hc = cc * 32;
        if (cc) __syncthreads();
#pragma unroll
        for (int p = 0; p < 8; p++) {
            const int r = lr + 8 * p;
            sSh[lk][r] = sLb[(size_t)r * HH + hc + lk];
        }
#pragma unroll
        for (int p = 0; p < 4; p++) {
            const int r = lr + 8 * p;
            tSh[lk][r] = tLb[(size_t)r * HH + hc + lk];
        }
        __syncthreads();

#pragma unroll 8
        for (int kk = 0; kk < 32; kk++) {
            const float w  = wrS[hc + kk];
            const float t0v = tSh[kk][ty * 2];
            const float t1v = tSh[kk][ty * 2 + 1];
#pragma unroll
            for (int i = 0; i < 4; i++) {
                const float sv = sSh[kk][tx * 4 + i];
                float y0, y1;
                tanh2_f16(t0v + sv, t1v + sv, y0, y1);
                a[0][i] = fmaf(w, y0, a[0][i]);
                a[1][i] = fmaf(w, y1, a[1][i]);
            }
        }
    }

    // ---- write partials ----
    const int t = t0 + ty * 2;
    const int s = s0 + tx * 4;
    const int idx = (b * TT + t) * SS + s;
#pragma unroll
    for (int j = 0; j < 2; j++) {
        float4 o = make_float4(a[j][0], a[j][1], a[j][2], a[j][3]);
        *(float4*)&g_part[hs * OUTN + idx + j * SS] = o;
    }

    // ---- ticket: last h-split block reduces the tile ----
    __threadfence();
    __syncthreads();
    const int tile = (b * (TT / 32) + blockIdx.y) * (SS / 64) + blockIdx.x;
    if (tid == 0) lastFlag = (atomicAdd(&g_cnt[tile], 1) == NHS - 1);
    __syncthreads();
    if (!lastFlag) return;

    const float bias = br[0];
    const float ninf = __int_as_float(0xff800000);
#pragma unroll
    for (int j = 0; j < 2; j++) {
        float4 acc4 = make_float4(0.f, 0.f, 0.f, 0.f);
#pragma unroll
        for (int h = 0; h < NHS; h++) {
            const float4 p = __ldcg((const float4*)&g_part[h * OUTN + idx + j * SS]);
            acc4.x += p.x; acc4.y += p.y; acc4.z += p.z; acc4.w += p.w;
        }
        float4 res;
        res.x = (__float_as_uint(maskF[b * SS + s])     != 0u) ? (acc4.x + bias) : ninf;
        res.y = (__float_as_uint(maskF[b * SS + s + 1]) != 0u) ? (acc4.y + bias) : ninf;
        res.z = (__float_as_uint(maskF[b * SS + s + 2]) != 0u) ? (acc4.z + bias) : ninf;
        res.w = (__float_as_uint(maskF[b * SS + s + 3]) != 0u) ? (acc4.w + bias) : ninf;
        *(float4*)&out[idx + j * SS] = res;
    }
    if (tid == 0) g_cnt[tile] = 0;   // reset for next graph replay
}

// ---------------- launch ----------------
extern "C" void kernel_launch(void* const* d_in, const int* in_sizes, int n_in,
                              void* d_out, int out_size) {
    const float* source = (const float*)d_in[0];  // [B,S,ES]
    const float* target = (const float*)d_in[1];  // [B,T,ET]
    const float* maskF  = (const float*)d_in[2];  // [B,S] bool (promoted to f32)
    const float* Ws     = (const float*)d_in[3];  // [H,ES]
    const float* Wt     = (const float*)d_in[4];  // [H,ET]
    const float* Wr     = (const float*)d_in[5];  // [H]
    const float* br     = (const float*)d_in[6];  // scalar
    const float* Wg     = (const float*)d_in[7];  // [2,ET]
    const float* bg     = (const float*)d_in[8];  // [2]

    float* out      = (float*)d_out;
    float* out_gate = out + (out_size - BB * TT * 2);

    proj_gate_kernel<<<GEMM_BLKS + 1, 256>>>(source, target, Ws, Wt, Wg, bg, out_gate);
    attn_kernel<<<dim3(SS / 64, TT / 32, BB * NHS), 256>>>(Wr, maskF, br, out);
}